// round 2
// baseline (speedup 1.0000x reference)
#include <cuda_runtime.h>

// ---------------------------------------------------------------------------
// NeuraLogicLayer: x0 = delta(0); 4x { x += relu(segment_sum(x[src]*W[widx], dst)) }
// Output: x[0].
//
// Sparse-propagation strategy: the active set (nonzero x) stays tiny (<~1K
// neurons), so each layer we only need to STREAM the src array (64MB) and test
// each src against a shared-memory hash of (active neuron -> x value).
// Hits (~5K/layer) do the actual message math. All device-global state is
// self-cleaning (restored to zero at the end of each call), so the launch is
// deterministic and graph-capturable with no memsets and no allocations.
// ---------------------------------------------------------------------------

#define NN          2000000
#define WTAB        1024
#define HASH_SLOTS  4096
#define HASH_MASK   (HASH_SLOTS - 1)
#define MAX_ACT     (1 << 20)
#define MAX_TOUCH   (1 << 20)

// Static device state (zero-initialized at module load; each kernel_launch
// call leaves it zeroed again except the counters, which k_init resets).
__device__ float         g_x[NN];         // sparse x values
__device__ float         g_out[NN];       // per-layer accumulator (self-cleaning)
__device__ unsigned char g_inlist[NN];    // membership flag for active list
__device__ int           g_act_list[MAX_ACT];
__device__ int           g_act_cnt;
__device__ int           g_tlist[2][MAX_TOUCH];  // double-buffered touched lists
__device__ int           g_tcnt[2];

__device__ __forceinline__ unsigned hash_nid(int nid) {
    return (((unsigned)nid * 2654435769u) >> 20) & HASH_MASK;
}

__global__ void k_init() {
    g_x[0]        = 1.0f;   // source neuron
    g_act_cnt     = 1;
    g_act_list[0] = 0;
    g_inlist[0]   = 1;
    g_tcnt[0]     = 0;
    g_tcnt[1]     = 0;
}

// Scan one layer: stream src, hash-probe each edge source against the active
// set; on hit, accumulate msg into g_out[dst] and record dst.
__global__ void __launch_bounds__(256)
k_scan(const int* __restrict__ src,
       const int* __restrict__ dst,
       const int* __restrict__ widx,
       const float* __restrict__ weights,
       int E, int parity)
{
    __shared__ int   s_key[HASH_SLOTS];
    __shared__ float s_val[HASH_SLOTS];
    __shared__ float s_w[WTAB];

    for (int i = threadIdx.x; i < HASH_SLOTS; i += blockDim.x) s_key[i] = -1;
    for (int i = threadIdx.x; i < WTAB; i += blockDim.x)       s_w[i]  = weights[i];
    __syncthreads();

    // Build shared hash of (active neuron -> x value).
    int cnt = g_act_cnt;
    if (cnt > MAX_ACT) cnt = MAX_ACT;
    for (int i = threadIdx.x; i < cnt; i += blockDim.x) {
        int   nid = g_act_list[i];
        float v   = g_x[nid];
        unsigned h = hash_nid(nid);
        for (int p = 0; p < HASH_SLOTS; p++) {
            int prev = atomicCAS(&s_key[h], -1, nid);
            if (prev == -1) { s_val[h] = v; break; }
            h = (h + 1) & HASH_MASK;
        }
    }
    __syncthreads();

    const int tid      = blockIdx.x * blockDim.x + threadIdx.x;
    const int nthreads = gridDim.x * blockDim.x;

    // Vectorized body: int4 streaming loads over src (read-once; keep out of L2).
    const int4* src4 = (const int4*)src;
    const int   n4   = E >> 2;
    for (int i = tid; i < n4; i += nthreads) {
        int4 s4 = __ldcs(&src4[i]);
        int ss[4] = { s4.x, s4.y, s4.z, s4.w };
        #pragma unroll
        for (int j = 0; j < 4; j++) {
            int s = ss[j];
            unsigned h = hash_nid(s);
            float xv = 0.0f;
            bool  hit = false;
            #pragma unroll 1
            for (int p = 0; p < HASH_SLOTS; p++) {
                int k = s_key[h];
                if (k == -1) break;
                if (k == s) { xv = s_val[h]; hit = true; break; }
                h = (h + 1) & HASH_MASK;
            }
            if (hit) {
                int e = (i << 2) + j;
                int d = __ldg(&dst[e]);
                int w = __ldg(&widx[e]);
                float msg = xv * s_w[w];
                atomicAdd(&g_out[d], msg);
                int pos = atomicAdd(&g_tcnt[parity], 1);
                if (pos < MAX_TOUCH) g_tlist[parity][pos] = d;
            }
        }
    }

    // Scalar tail (E not multiple of 4).
    for (int e = (n4 << 2) + tid; e < E; e += nthreads) {
        int s = src[e];
        unsigned h = hash_nid(s);
        float xv = 0.0f;
        bool  hit = false;
        for (int p = 0; p < HASH_SLOTS; p++) {
            int k = s_key[h];
            if (k == -1) break;
            if (k == s) { xv = s_val[h]; hit = true; break; }
            h = (h + 1) & HASH_MASK;
        }
        if (hit) {
            int d = dst[e];
            int w = widx[e];
            atomicAdd(&g_out[d], xv * s_w[w]);
            int pos = atomicAdd(&g_tcnt[parity], 1);
            if (pos < MAX_TOUCH) g_tlist[parity][pos] = d;
        }
    }
}

// Apply x += relu(out) for all touched destinations; dedup & self-clean g_out
// via atomicExch (exactly one thread per distinct d grabs the nonzero sum).
// Also zeroes the OTHER parity's touched counter for the next layer.
__global__ void k_update(int parity) {
    int cnt = g_tcnt[parity];
    if (cnt > MAX_TOUCH) cnt = MAX_TOUCH;
    int tid    = blockIdx.x * blockDim.x + threadIdx.x;
    int stride = gridDim.x * blockDim.x;
    if (tid == 0) g_tcnt[parity ^ 1] = 0;
    for (int i = tid; i < cnt; i += stride) {
        int   d   = g_tlist[parity][i];
        float val = atomicExch(&g_out[d], 0.0f);
        if (val > 0.0f) {
            g_x[d] += val;       // unique grabber per d -> plain RMW is safe
            if (!g_inlist[d]) {
                g_inlist[d] = 1;
                int pos = atomicAdd(&g_act_cnt, 1);
                if (pos < MAX_ACT) g_act_list[pos] = d;
            }
        }
    }
}

// Emit the answer and restore all touched global state to zero so the next
// (graph-replayed) call starts from a clean slate. g_act_list[0] is always
// neuron 0, so the thread handling i==0 writes the output before clearing.
__global__ void k_finish(float* out) {
    int cnt = g_act_cnt;
    if (cnt > MAX_ACT) cnt = MAX_ACT;
    int tid    = blockIdx.x * blockDim.x + threadIdx.x;
    int stride = gridDim.x * blockDim.x;
    for (int i = tid; i < cnt; i += stride) {
        int d = g_act_list[i];
        if (i == 0) out[0] = g_x[d];   // d == 0 here by construction
        g_x[d]      = 0.0f;
        g_inlist[d] = 0;
    }
}

extern "C" void kernel_launch(void* const* d_in, const int* in_sizes, int n_in,
                              void* d_out, int out_size) {
    const float* weights = (const float*)d_in[0];
    const int*   src     = (const int*)d_in[1];
    const int*   dst     = (const int*)d_in[2];
    const int*   widx    = (const int*)d_in[3];
    float*       out     = (float*)d_out;

    const int L = 4;
    const int E = in_sizes[1] / L;

    // 36KB smem/block -> 6 blocks/SM on 148 SMs.
    const int SCAN_BLOCKS = 148 * 6;

    k_init<<<1, 1>>>();
    for (int l = 0; l < L; l++) {
        int parity = l & 1;
        k_scan<<<SCAN_BLOCKS, 256>>>(src + (size_t)l * E,
                                     dst + (size_t)l * E,
                                     widx + (size_t)l * E,
                                     weights, E, parity);
        k_update<<<32, 256>>>(parity);
    }
    k_finish<<<32, 256>>>(out);
}

// round 5
// speedup vs baseline: 1.2994x; 1.2994x over previous
#include <cuda_runtime.h>

// ---------------------------------------------------------------------------
// NeuraLogicLayer: x0 = delta(0); 4x { x += relu(segment_sum(x[src]*W[widx], dst)) }
// Output: x[0].
//
// Sparse propagation. Active set stays tiny (<~1K neurons), so each layer only
// streams ONE 64MB index array and filters it:
//   L1: src==0 test (x is a delta at 0)            -> min-tree, ~1.5 instr/edge
//   L2,L3: branchless 1-probe shared hash of active ids; collisions marked -2,
//          resolved via dense g_x[] in L2          -> ~7 instr/edge
//   L4: dst==0 test (only x[0] is returned)        -> min-tree, ~1.5 instr/edge
// All device-global state is self-cleaning, so the launch is deterministic and
// graph-capturable with no memsets and no allocations.
// ---------------------------------------------------------------------------

#define NN          2000000
#define HASH_BITS   13
#define HASH_SLOTS  (1 << HASH_BITS)
#define MAX_ACT     (1 << 20)
#define MAX_TOUCH   (1 << 20)

__device__ float         g_x[NN];         // dense x (sparse content, self-cleaned)
__device__ float         g_out[NN];       // per-layer accumulator (self-cleaned)
__device__ unsigned char g_inlist[NN];
__device__ int           g_act_list[MAX_ACT];
__device__ int           g_act_cnt;
__device__ int           g_tlist[2][MAX_TOUCH];
__device__ int           g_tcnt[2];

__device__ __forceinline__ unsigned hash_nid(int nid) {
    return ((unsigned)nid * 2654435769u) >> (32 - HASH_BITS);
}

__global__ void k_init() {
    g_x[0]        = 1.0f;
    g_act_cnt     = 1;
    g_act_list[0] = 0;
    g_inlist[0]   = 1;
    g_tcnt[0]     = 0;
    g_tcnt[1]     = 0;
}

// ---- full edge processing for one hit (rare). Warp-aggregated counter. ----
// Called under divergence; uses __activemask() coalesced-group aggregation.
__device__ __forceinline__ void do_hit(float xv, int e,
                                       const int* __restrict__ dst,
                                       const int* __restrict__ widx,
                                       const float* __restrict__ weights,
                                       int parity)
{
    int   d   = __ldg(&dst[e]);
    int   w   = __ldg(&widx[e]);
    float msg = xv * __ldg(&weights[w]);
    atomicAdd(&g_out[d], msg);

    unsigned mask   = __activemask();
    unsigned lane   = threadIdx.x & 31u;
    unsigned before = mask & ((1u << lane) - 1u);
    int      leader = __ffs(mask) - 1;
    int base = 0;
    if ((int)lane == leader)
        base = atomicAdd(&g_tcnt[parity], __popc(mask));
    base = __shfl_sync(mask, base, leader);
    int pos = base + __popc(before);
    if (pos < MAX_TOUCH) g_tlist[parity][pos] = d;
}

// ---- Layer 1: only src==0 carries a message (x = delta at neuron 0) -------
__global__ void __launch_bounds__(256)
k_scan_l1(const int* __restrict__ src,
          const int* __restrict__ dst,
          const int* __restrict__ widx,
          const float* __restrict__ weights,
          int E, int parity)
{
    const int tid = blockIdx.x * blockDim.x + threadIdx.x;
    const int nth = gridDim.x * blockDim.x;
    const int4* s4p = (const int4*)src;
    const int n8 = E >> 3;
    for (int i = tid; i < n8; i += nth) {
        int4 a = __ldcs(&s4p[2 * i]);
        int4 b = __ldcs(&s4p[2 * i + 1]);
        int m = min(min(min(a.x, a.y), min(a.z, a.w)),
                    min(min(b.x, b.y), min(b.z, b.w)));
        if (m == 0) {                       // some src in this group is 0
            int s[8] = {a.x, a.y, a.z, a.w, b.x, b.y, b.z, b.w};
            #pragma unroll
            for (int j = 0; j < 8; j++)
                if (s[j] == 0) do_hit(1.0f, (i << 3) + j, dst, widx, weights, parity);
        }
    }
    for (int e = (n8 << 3) + tid; e < E; e += nth)
        if (src[e] == 0) do_hit(1.0f, e, dst, widx, weights, parity);
}

// ---- Layer 4: only dst==0 affects the answer ------------------------------
__global__ void __launch_bounds__(256)
k_scan_l4(const int* __restrict__ src,
          const int* __restrict__ dst,
          const int* __restrict__ widx,
          const float* __restrict__ weights,
          int E, int parity)
{
    const int tid = blockIdx.x * blockDim.x + threadIdx.x;
    const int nth = gridDim.x * blockDim.x;
    const int4* d4p = (const int4*)dst;
    const int n8 = E >> 3;
    for (int i = tid; i < n8; i += nth) {
        int4 a = __ldcs(&d4p[2 * i]);
        int4 b = __ldcs(&d4p[2 * i + 1]);
        int m = min(min(min(a.x, a.y), min(a.z, a.w)),
                    min(min(b.x, b.y), min(b.z, b.w)));
        if (m == 0) {
            int d[8] = {a.x, a.y, a.z, a.w, b.x, b.y, b.z, b.w};
            #pragma unroll
            for (int j = 0; j < 8; j++) {
                if (d[j] == 0) {
                    int e = (i << 3) + j;
                    int s = __ldg(&src[e]);
                    float xv = __ldg(&g_x[s]);
                    if (xv != 0.0f)
                        do_hit(xv, e, dst, widx, weights, parity);
                }
            }
        }
    }
    for (int e = (n8 << 3) + tid; e < E; e += nth) {
        if (dst[e] == 0) {
            float xv = __ldg(&g_x[src[e]]);
            if (xv != 0.0f) do_hit(xv, e, dst, widx, weights, parity);
        }
    }
}

// ---- Layers 2,3: branchless 1-probe hash membership -----------------------
// Slot states: -1 empty, -2 collision (resolve via g_x), nid = sole resident.
__global__ void __launch_bounds__(256)
k_scan_hash(const int* __restrict__ src,
            const int* __restrict__ dst,
            const int* __restrict__ widx,
            const float* __restrict__ weights,
            int E, int parity)
{
    __shared__ int s_key[HASH_SLOTS];
    for (int i = threadIdx.x; i < HASH_SLOTS; i += blockDim.x) s_key[i] = -1;
    __syncthreads();

    int cnt = g_act_cnt;
    if (cnt > MAX_ACT) cnt = MAX_ACT;
    for (int i = threadIdx.x; i < cnt; i += blockDim.x) {
        int nid = g_act_list[i];
        unsigned h = hash_nid(nid);
        int old = atomicCAS(&s_key[h], -1, nid);
        if (old != -1 && old != nid)
            atomicExch(&s_key[h], -2);   // any collision -> fall back to g_x
    }
    __syncthreads();

    const int tid = blockIdx.x * blockDim.x + threadIdx.x;
    const int nth = gridDim.x * blockDim.x;
    const int4* s4p = (const int4*)src;
    const int n8 = E >> 3;
    for (int i = tid; i < n8; i += nth) {
        int4 a = __ldcs(&s4p[2 * i]);
        int4 b = __ldcs(&s4p[2 * i + 1]);
        int s[8] = {a.x, a.y, a.z, a.w, b.x, b.y, b.z, b.w};
        int  k[8];
        bool c[8];
        #pragma unroll
        for (int j = 0; j < 8; j++) k[j] = s_key[hash_nid(s[j])];
        bool any = false;
        #pragma unroll
        for (int j = 0; j < 8; j++) {
            c[j] = (k[j] == s[j]) | (k[j] == -2);
            any |= c[j];
        }
        if (any) {                          // rare: candidate hit or collision slot
            #pragma unroll
            for (int j = 0; j < 8; j++) {
                if (c[j]) {
                    float xv = __ldg(&g_x[s[j]]);   // dense ground truth (L2)
                    if (xv != 0.0f)
                        do_hit(xv, (i << 3) + j, dst, widx, weights, parity);
                }
            }
        }
    }
    for (int e = (n8 << 3) + tid; e < E; e += nth) {
        int s = src[e];
        int k = s_key[hash_nid(s)];
        if ((k == s) | (k == -2)) {
            float xv = __ldg(&g_x[s]);
            if (xv != 0.0f) do_hit(xv, e, dst, widx, weights, parity);
        }
    }
}

// ---- apply x += relu(out); dedup + self-clean via atomicExch --------------
__global__ void k_update(int parity) {
    int cnt = g_tcnt[parity];
    if (cnt > MAX_TOUCH) cnt = MAX_TOUCH;
    int tid    = blockIdx.x * blockDim.x + threadIdx.x;
    int stride = gridDim.x * blockDim.x;
    if (tid == 0) g_tcnt[parity ^ 1] = 0;
    for (int i = tid; i < cnt; i += stride) {
        int   d   = g_tlist[parity][i];
        float val = atomicExch(&g_out[d], 0.0f);
        if (val > 0.0f) {
            g_x[d] += val;          // unique grabber per d
            if (!g_inlist[d]) {
                g_inlist[d] = 1;
                int pos = atomicAdd(&g_act_cnt, 1);
                if (pos < MAX_ACT) g_act_list[pos] = d;
            }
        }
    }
}

// ---- emit answer, restore all touched state to zero -----------------------
__global__ void k_finish(float* out) {
    int cnt = g_act_cnt;
    if (cnt > MAX_ACT) cnt = MAX_ACT;
    int tid    = blockIdx.x * blockDim.x + threadIdx.x;
    int stride = gridDim.x * blockDim.x;
    for (int i = tid; i < cnt; i += stride) {
        int d = g_act_list[i];
        if (i == 0) out[0] = g_x[d];   // g_act_list[0] == 0 by construction
        g_x[d]      = 0.0f;
        g_inlist[d] = 0;
    }
}

extern "C" void kernel_launch(void* const* d_in, const int* in_sizes, int n_in,
                              void* d_out, int out_size) {
    const float* weights = (const float*)d_in[0];
    const int*   src     = (const int*)d_in[1];
    const int*   dst     = (const int*)d_in[2];
    const int*   widx    = (const int*)d_in[3];
    float*       out     = (float*)d_out;

    const int L = 4;
    const int E = in_sizes[1] / L;

    const int CHEAP_BLOCKS = 148 * 8;   // no smem
    const int HASH_BLOCKS  = 148 * 6;   // 32KB smem/block

    k_init<<<1, 1>>>();

    // layer 0 (parity 0): delta source -> src==0 filter
    k_scan_l1<<<CHEAP_BLOCKS, 256>>>(src, dst, widx, weights, E, 0);
    k_update<<<32, 256>>>(0);

    // layer 1 (parity 1)
    k_scan_hash<<<HASH_BLOCKS, 256>>>(src + (size_t)1 * E, dst + (size_t)1 * E,
                                      widx + (size_t)1 * E, weights, E, 1);
    k_update<<<32, 256>>>(1);

    // layer 2 (parity 0)
    k_scan_hash<<<HASH_BLOCKS, 256>>>(src + (size_t)2 * E, dst + (size_t)2 * E,
                                      widx + (size_t)2 * E, weights, E, 0);
    k_update<<<32, 256>>>(0);

    // layer 3 (parity 1): only dst==0 matters for the answer
    k_scan_l4<<<CHEAP_BLOCKS, 256>>>(src + (size_t)3 * E, dst + (size_t)3 * E,
                                     widx + (size_t)3 * E, weights, E, 1);
    k_update<<<32, 256>>>(1);

    k_finish<<<32, 256>>>(out);
}